// round 6
// baseline (speedup 1.0000x reference)
#include <cuda_runtime.h>

// Fused LatentDynamicsModel:
//   x      = relu([z|a] @ W_in^T + b_in)
//   gi     = x @ W_ih^T + b_ih ; gh = h @ W_hh^T + b_hh   (gates r,z,n)
//   r      = sigmoid(i_r + h_r); zg = sigmoid(i_z + h_z)
//   n      = tanh(i_n + r * h_n)
//   h_new  = (1-zg)*n + zg*h
//   y      = relu(h_new @ W_o1^T + b_o1)
//   z_next = y @ W_o2^T + b_o2
// Output layout: d_out[0 : B*64) = z_next, d_out[B*64 : B*64+B*256) = h_new.

#define HID     256
#define LATENT  64
#define ACT     2
#define TM      32      // rows per CTA
#define THREADS 256

// SMEM float counts
#define ZA_LD   96                 // padded K for input projection (66 real)
#define WST_LD  257                // transposed weight tile leading dim

__device__ __forceinline__ float sigmoidf_(float x) {
    return 1.0f / (1.0f + __expf(-x));
}

// Accumulate acc[4][NJ] += As[TM x K] @ W^T chunk.
// W: row-major [N rows, ldw cols], N = NJ*32 rows used.
// As: smem, lda stride. K covered in tiles of 32 (Ktiles tiles), zero-padded
// beyond Kreal (As must be zero-padded to Ktiles*32 columns as well).
// Thread mapping: c = lane (0..31), rg4 = 4*(warp id) -> rows rg4..rg4+3,
// cols n = c + 32*j.
template <int NJ>
__device__ __forceinline__ void gemm_acc(
    float acc[4][NJ],
    const float* __restrict__ W, int ldw, int Kreal, int Ktiles,
    const float* __restrict__ As, int lda,
    float* __restrict__ Wst, int tid, int c, int rg4)
{
    for (int t = 0; t < Ktiles; ++t) {
        const int k0 = t * 32;
        // Cooperative transposed load of W tile [32 k x NJ*32 n] -> Wst[kk][n]
        #pragma unroll
        for (int i = 0; i < NJ; ++i) {
            int id  = tid + THREADS * i;      // [0, NJ*256)
            int kk4 = (id & 7) * 4;           // k offset within tile (x4)
            int n   = id >> 3;                // weight row
            int kb  = k0 + kk4;
            const float* wp = W + (long)n * ldw + kb;
            float v0 = (kb + 0 < Kreal) ? wp[0] : 0.0f;
            float v1 = (kb + 1 < Kreal) ? wp[1] : 0.0f;
            float v2 = (kb + 2 < Kreal) ? wp[2] : 0.0f;
            float v3 = (kb + 3 < Kreal) ? wp[3] : 0.0f;
            Wst[(kk4 + 0) * WST_LD + n] = v0;
            Wst[(kk4 + 1) * WST_LD + n] = v1;
            Wst[(kk4 + 2) * WST_LD + n] = v2;
            Wst[(kk4 + 3) * WST_LD + n] = v3;
        }
        __syncthreads();

        const float* a0p = As + (rg4 + 0) * lda + k0;
        const float* a1p = As + (rg4 + 1) * lda + k0;
        const float* a2p = As + (rg4 + 2) * lda + k0;
        const float* a3p = As + (rg4 + 3) * lda + k0;
        #pragma unroll 8
        for (int kk = 0; kk < 32; ++kk) {
            float a0 = a0p[kk];   // warp-uniform (broadcast)
            float a1 = a1p[kk];
            float a2 = a2p[kk];
            float a3 = a3p[kk];
            const float* wrow = Wst + kk * WST_LD + c;
            #pragma unroll
            for (int j = 0; j < NJ; ++j) {
                float w = wrow[32 * j];       // lane-consecutive: conflict-free
                acc[0][j] += a0 * w;
                acc[1][j] += a1 * w;
                acc[2][j] += a2 * w;
                acc[3][j] += a3 * w;
            }
        }
        __syncthreads();
    }
}

__global__ __launch_bounds__(THREADS, 1)
void latent_dynamics_kernel(
    const float* __restrict__ z,
    const float* __restrict__ action,
    const float* __restrict__ hidden,
    const float* __restrict__ W_in,  const float* __restrict__ b_in,
    const float* __restrict__ W_ih,  const float* __restrict__ W_hh,
    const float* __restrict__ b_ih,  const float* __restrict__ b_hh,
    const float* __restrict__ W_o1,  const float* __restrict__ b_o1,
    const float* __restrict__ W_o2,  const float* __restrict__ b_o2,
    float* __restrict__ out_z,       // [B, 64]
    float* __restrict__ out_h)       // [B, 256]
{
    extern __shared__ float smem[];
    float* As_x = smem;                      // TM*HID     = 8192
    float* As_h = As_x + TM * HID;           // TM*HID     = 8192
    float* HN   = As_h + TM * HID;           // TM*HID     = 8192
    float* za   = HN   + TM * HID;           // TM*ZA_LD   = 3072
    float* Wst  = za   + TM * ZA_LD;         // 32*WST_LD  = 8224

    const int tid  = threadIdx.x;
    const int c    = tid & 31;          // lane
    const int rg4  = (tid >> 5) * 4;    // first of 4 rows this thread owns
    const long row0 = (long)blockIdx.x * TM;

    // ---- load inputs: za = [z | action | 0-pad], As_h = h tile ----
    for (int id = tid; id < TM * ZA_LD; id += THREADS) {
        int r = id / ZA_LD, cc = id - r * ZA_LD;
        float v = 0.0f;
        long gr = row0 + r;
        if (cc < LATENT)            v = z[gr * LATENT + cc];
        else if (cc < LATENT + ACT) v = action[gr * ACT + (cc - LATENT)];
        za[id] = v;
    }
    for (int id = tid; id < TM * HID; id += THREADS) {
        int r = id >> 8, cc = id & 255;
        As_h[id] = hidden[(row0 + r) * HID + cc];
    }
    __syncthreads();

    float acc[4][8];

    // ---- P0: x = relu([z|a] @ W_in^T + b_in) ----
    #pragma unroll
    for (int i = 0; i < 4; ++i)
        #pragma unroll
        for (int j = 0; j < 8; ++j) acc[i][j] = 0.0f;
    gemm_acc<8>(acc, W_in, LATENT + ACT, LATENT + ACT, 3, za, ZA_LD, Wst, tid, c, rg4);
    #pragma unroll
    for (int j = 0; j < 8; ++j) {
        int n = c + 32 * j;
        float b = b_in[n];
        #pragma unroll
        for (int i = 0; i < 4; ++i)
            As_x[(rg4 + i) * HID + n] = fmaxf(acc[i][j] + b, 0.0f);
    }
    __syncthreads();

    // ---- P1: HN = h @ W_hh_n^T + b_hh_n ----
    #pragma unroll
    for (int i = 0; i < 4; ++i)
        #pragma unroll
        for (int j = 0; j < 8; ++j) acc[i][j] = 0.0f;
    gemm_acc<8>(acc, W_hh + 2 * HID * HID, HID, HID, 8, As_h, HID, Wst, tid, c, rg4);
    #pragma unroll
    for (int j = 0; j < 8; ++j) {
        int n = c + 32 * j;
        float b = b_hh[2 * HID + n];
        #pragma unroll
        for (int i = 0; i < 4; ++i)
            HN[(rg4 + i) * HID + n] = acc[i][j] + b;
    }
    // no sync needed: HN elements are thread-private across P1..P4

    // ---- P2: r = sigmoid(x@W_ih_r^T + h@W_hh_r^T + b); HN *= r ----
    #pragma unroll
    for (int i = 0; i < 4; ++i)
        #pragma unroll
        for (int j = 0; j < 8; ++j) acc[i][j] = 0.0f;
    gemm_acc<8>(acc, W_ih, HID, HID, 8, As_x, HID, Wst, tid, c, rg4);
    gemm_acc<8>(acc, W_hh, HID, HID, 8, As_h, HID, Wst, tid, c, rg4);
    #pragma unroll
    for (int j = 0; j < 8; ++j) {
        int n = c + 32 * j;
        float b = b_ih[n] + b_hh[n];
        #pragma unroll
        for (int i = 0; i < 4; ++i) {
            float r = sigmoidf_(acc[i][j] + b);
            HN[(rg4 + i) * HID + n] *= r;
        }
    }

    // ---- P3: n = tanh(x@W_ih_n^T + b_ih_n + r*h_n); HN = n ----
    #pragma unroll
    for (int i = 0; i < 4; ++i)
        #pragma unroll
        for (int j = 0; j < 8; ++j) acc[i][j] = 0.0f;
    gemm_acc<8>(acc, W_ih + 2 * HID * HID, HID, HID, 8, As_x, HID, Wst, tid, c, rg4);
    #pragma unroll
    for (int j = 0; j < 8; ++j) {
        int n = c + 32 * j;
        float b = b_ih[2 * HID + n];
        #pragma unroll
        for (int i = 0; i < 4; ++i) {
            int idx = (rg4 + i) * HID + n;
            HN[idx] = tanhf(acc[i][j] + b + HN[idx]);
        }
    }

    // ---- P4: zg = sigmoid(x@W_ih_z^T + h@W_hh_z^T + b); h_new ----
    #pragma unroll
    for (int i = 0; i < 4; ++i)
        #pragma unroll
        for (int j = 0; j < 8; ++j) acc[i][j] = 0.0f;
    gemm_acc<8>(acc, W_ih + 1 * HID * HID, HID, HID, 8, As_x, HID, Wst, tid, c, rg4);
    gemm_acc<8>(acc, W_hh + 1 * HID * HID, HID, HID, 8, As_h, HID, Wst, tid, c, rg4);
    #pragma unroll
    for (int j = 0; j < 8; ++j) {
        int n = c + 32 * j;
        float b = b_ih[HID + n] + b_hh[HID + n];
        #pragma unroll
        for (int i = 0; i < 4; ++i) {
            int idx = (rg4 + i) * HID + n;
            float zg    = sigmoidf_(acc[i][j] + b);
            float hprev = As_h[idx];
            float hnew  = (1.0f - zg) * HN[idx] + zg * hprev;
            out_h[(row0 + rg4 + i) * HID + n] = hnew;
            As_x[idx] = hnew;   // reuse As_x as h_new for the output head
        }
    }
    __syncthreads();

    // ---- P5: y = relu(h_new @ W_o1^T + b_o1) -> As_h ----
    #pragma unroll
    for (int i = 0; i < 4; ++i)
        #pragma unroll
        for (int j = 0; j < 8; ++j) acc[i][j] = 0.0f;
    gemm_acc<8>(acc, W_o1, HID, HID, 8, As_x, HID, Wst, tid, c, rg4);
    #pragma unroll
    for (int j = 0; j < 8; ++j) {
        int n = c + 32 * j;
        float b = b_o1[n];
        #pragma unroll
        for (int i = 0; i < 4; ++i)
            As_h[(rg4 + i) * HID + n] = fmaxf(acc[i][j] + b, 0.0f);
    }
    __syncthreads();

    // ---- P6: z_next = y @ W_o2^T + b_o2 (N = 64) ----
    float acc2[4][2];
    #pragma unroll
    for (int i = 0; i < 4; ++i) { acc2[i][0] = 0.0f; acc2[i][1] = 0.0f; }
    gemm_acc<2>(acc2, W_o2, HID, HID, 8, As_h, HID, Wst, tid, c, rg4);
    #pragma unroll
    for (int j = 0; j < 2; ++j) {
        int n = c + 32 * j;
        float b = b_o2[n];
        #pragma unroll
        for (int i = 0; i < 4; ++i)
            out_z[(row0 + rg4 + i) * LATENT + n] = acc2[i][j] + b;
    }
}

extern "C" void kernel_launch(void* const* d_in, const int* in_sizes, int n_in,
                              void* d_out, int out_size) {
    const float* z      = (const float*)d_in[0];
    const float* action = (const float*)d_in[1];
    const float* hidden = (const float*)d_in[2];
    const float* W_in   = (const float*)d_in[3];
    const float* b_in   = (const float*)d_in[4];
    const float* W_ih   = (const float*)d_in[5];
    const float* W_hh   = (const float*)d_in[6];
    const float* b_ih   = (const float*)d_in[7];
    const float* b_hh   = (const float*)d_in[8];
    const float* W_o1   = (const float*)d_in[9];
    const float* b_o1   = (const float*)d_in[10];
    const float* W_o2   = (const float*)d_in[11];
    const float* b_o2   = (const float*)d_in[12];

    const int B = in_sizes[0] / LATENT;   // 131072
    float* out_z = (float*)d_out;                      // [B, 64]
    float* out_h = (float*)d_out + (long)B * LATENT;   // [B, 256]

    const int smem_bytes = (3 * TM * HID + TM * ZA_LD + 32 * WST_LD) * sizeof(float);
    static bool attr_set = false;
    // idempotent, not an allocation, executes immediately (not captured)
    cudaFuncSetAttribute(latent_dynamics_kernel,
                         cudaFuncAttributeMaxDynamicSharedMemorySize, smem_bytes);
    (void)attr_set;

    dim3 grid(B / TM);
    latent_dynamics_kernel<<<grid, THREADS, smem_bytes>>>(
        z, action, hidden, W_in, b_in, W_ih, W_hh, b_ih, b_hh,
        W_o1, b_o1, W_o2, b_o2, out_z, out_h);
}

// round 7
// speedup vs baseline: 1.2132x; 1.2132x over previous
#include <cuda_runtime.h>

// Fused LatentDynamicsModel:
//   x      = relu([z|a] @ W_in^T + b_in)
//   gi     = x @ W_ih^T + b_ih ; gh = h @ W_hh^T + b_hh   (gates r,z,n)
//   r      = sigmoid(i_r + h_r); zg = sigmoid(i_z + h_z)
//   n      = tanh(i_n + r * h_n)
//   h_new  = (1-zg)*n + zg*h
//   y      = relu(h_new @ W_o1^T + b_o1)
//   z_next = y @ W_o2^T + b_o2
// Output layout: d_out[0 : B*64) = z_next, d_out[B*64 : B*64+B*256) = h_new.
//
// R6: HN accumulator moved from SMEM to registers (thread-private), za aliased
// onto As_x (temporally disjoint), smem 143KB -> 96KB => 2 CTAs/SM.

#define HID     256
#define LATENT  64
#define ACT     2
#define TM      32      // rows per CTA
#define THREADS 256

// SMEM float counts
#define ZA_LD   96                 // padded K for input projection (66 real)
#define WST_LD  257                // transposed weight tile leading dim

__device__ __forceinline__ float sigmoidf_(float x) {
    return 1.0f / (1.0f + __expf(-x));
}

// Accumulate acc[4][NJ] += As[TM x K] @ W^T chunk.
// W: row-major [N rows, ldw cols], N = NJ*32 rows used.
// As: smem, lda stride. K covered in tiles of 32 (Ktiles tiles), zero-padded
// beyond Kreal (As must be zero-padded to Ktiles*32 columns as well).
// Thread mapping: c = lane (0..31), rg4 = 4*(warp id) -> rows rg4..rg4+3,
// cols n = c + 32*j.
template <int NJ>
__device__ __forceinline__ void gemm_acc(
    float acc[4][NJ],
    const float* __restrict__ W, int ldw, int Kreal, int Ktiles,
    const float* __restrict__ As, int lda,
    float* __restrict__ Wst, int tid, int c, int rg4)
{
    for (int t = 0; t < Ktiles; ++t) {
        const int k0 = t * 32;
        // Cooperative transposed load of W tile [32 k x NJ*32 n] -> Wst[kk][n]
        #pragma unroll
        for (int i = 0; i < NJ; ++i) {
            int id  = tid + THREADS * i;      // [0, NJ*256)
            int kk4 = (id & 7) * 4;           // k offset within tile (x4)
            int n   = id >> 3;                // weight row
            int kb  = k0 + kk4;
            const float* wp = W + (long)n * ldw + kb;
            float v0 = (kb + 0 < Kreal) ? wp[0] : 0.0f;
            float v1 = (kb + 1 < Kreal) ? wp[1] : 0.0f;
            float v2 = (kb + 2 < Kreal) ? wp[2] : 0.0f;
            float v3 = (kb + 3 < Kreal) ? wp[3] : 0.0f;
            Wst[(kk4 + 0) * WST_LD + n] = v0;
            Wst[(kk4 + 1) * WST_LD + n] = v1;
            Wst[(kk4 + 2) * WST_LD + n] = v2;
            Wst[(kk4 + 3) * WST_LD + n] = v3;
        }
        __syncthreads();

        const float* a0p = As + (rg4 + 0) * lda + k0;
        const float* a1p = As + (rg4 + 1) * lda + k0;
        const float* a2p = As + (rg4 + 2) * lda + k0;
        const float* a3p = As + (rg4 + 3) * lda + k0;
        #pragma unroll 8
        for (int kk = 0; kk < 32; ++kk) {
            float a0 = a0p[kk];   // warp-uniform (broadcast)
            float a1 = a1p[kk];
            float a2 = a2p[kk];
            float a3 = a3p[kk];
            const float* wrow = Wst + kk * WST_LD + c;
            #pragma unroll
            for (int j = 0; j < NJ; ++j) {
                float w = wrow[32 * j];       // lane-consecutive: conflict-free
                acc[0][j] += a0 * w;
                acc[1][j] += a1 * w;
                acc[2][j] += a2 * w;
                acc[3][j] += a3 * w;
            }
        }
        __syncthreads();
    }
}

__global__ __launch_bounds__(THREADS, 2)
void latent_dynamics_kernel(
    const float* __restrict__ z,
    const float* __restrict__ action,
    const float* __restrict__ hidden,
    const float* __restrict__ W_in,  const float* __restrict__ b_in,
    const float* __restrict__ W_ih,  const float* __restrict__ W_hh,
    const float* __restrict__ b_ih,  const float* __restrict__ b_hh,
    const float* __restrict__ W_o1,  const float* __restrict__ b_o1,
    const float* __restrict__ W_o2,  const float* __restrict__ b_o2,
    float* __restrict__ out_z,       // [B, 64]
    float* __restrict__ out_h)       // [B, 256]
{
    extern __shared__ float smem[];
    float* As_x = smem;                      // TM*HID     = 8192 floats
    float* As_h = As_x + TM * HID;           // TM*HID     = 8192
    float* Wst  = As_h + TM * HID;           // 32*WST_LD  = 8224
    float* za   = As_x;                      // ALIAS: za (3072 floats) lives in
                                             // As_x; all za reads finish at the
                                             // barrier before As_x is written.

    const int tid  = threadIdx.x;
    const int c    = tid & 31;          // lane
    const int rg4  = (tid >> 5) * 4;    // first of 4 rows this thread owns
    const long row0 = (long)blockIdx.x * TM;

    // ---- load inputs: za = [z | action | 0-pad], As_h = h tile ----
    for (int id = tid; id < TM * ZA_LD; id += THREADS) {
        int r = id / ZA_LD, cc = id - r * ZA_LD;
        float v = 0.0f;
        long gr = row0 + r;
        if (cc < LATENT)            v = z[gr * LATENT + cc];
        else if (cc < LATENT + ACT) v = action[gr * ACT + (cc - LATENT)];
        za[id] = v;
    }
    for (int id = tid; id < TM * HID; id += THREADS) {
        int r = id >> 8, cc = id & 255;
        As_h[id] = hidden[(row0 + r) * HID + cc];
    }
    __syncthreads();

    float acc[4][8];
    float hn[4][8];     // register-resident HN (thread-private across P1..P4)

    // ---- P0: x = relu([z|a] @ W_in^T + b_in) ----
    #pragma unroll
    for (int i = 0; i < 4; ++i)
        #pragma unroll
        for (int j = 0; j < 8; ++j) acc[i][j] = 0.0f;
    gemm_acc<8>(acc, W_in, LATENT + ACT, LATENT + ACT, 3, za, ZA_LD, Wst, tid, c, rg4);
    // gemm_acc ends with __syncthreads(): all za reads complete before we
    // overwrite the aliased As_x region below.
    #pragma unroll
    for (int j = 0; j < 8; ++j) {
        int n = c + 32 * j;
        float b = b_in[n];
        #pragma unroll
        for (int i = 0; i < 4; ++i)
            As_x[(rg4 + i) * HID + n] = fmaxf(acc[i][j] + b, 0.0f);
    }
    __syncthreads();

    // ---- P1: hn = h @ W_hh_n^T + b_hh_n ----
    #pragma unroll
    for (int i = 0; i < 4; ++i)
        #pragma unroll
        for (int j = 0; j < 8; ++j) acc[i][j] = 0.0f;
    gemm_acc<8>(acc, W_hh + 2 * HID * HID, HID, HID, 8, As_h, HID, Wst, tid, c, rg4);
    #pragma unroll
    for (int j = 0; j < 8; ++j) {
        int n = c + 32 * j;
        float b = b_hh[2 * HID + n];
        #pragma unroll
        for (int i = 0; i < 4; ++i)
            hn[i][j] = acc[i][j] + b;
    }

    // ---- P2: r = sigmoid(x@W_ih_r^T + h@W_hh_r^T + b); hn *= r ----
    #pragma unroll
    for (int i = 0; i < 4; ++i)
        #pragma unroll
        for (int j = 0; j < 8; ++j) acc[i][j] = 0.0f;
    gemm_acc<8>(acc, W_ih, HID, HID, 8, As_x, HID, Wst, tid, c, rg4);
    gemm_acc<8>(acc, W_hh, HID, HID, 8, As_h, HID, Wst, tid, c, rg4);
    #pragma unroll
    for (int j = 0; j < 8; ++j) {
        int n = c + 32 * j;
        float b = b_ih[n] + b_hh[n];
        #pragma unroll
        for (int i = 0; i < 4; ++i) {
            float r = sigmoidf_(acc[i][j] + b);
            hn[i][j] *= r;
        }
    }

    // ---- P3: n = tanh(x@W_ih_n^T + b_ih_n + r*h_n); hn = n ----
    #pragma unroll
    for (int i = 0; i < 4; ++i)
        #pragma unroll
        for (int j = 0; j < 8; ++j) acc[i][j] = 0.0f;
    gemm_acc<8>(acc, W_ih + 2 * HID * HID, HID, HID, 8, As_x, HID, Wst, tid, c, rg4);
    #pragma unroll
    for (int j = 0; j < 8; ++j) {
        int n = c + 32 * j;
        float b = b_ih[2 * HID + n];
        #pragma unroll
        for (int i = 0; i < 4; ++i)
            hn[i][j] = tanhf(acc[i][j] + b + hn[i][j]);
    }

    // ---- P4: zg = sigmoid(x@W_ih_z^T + h@W_hh_z^T + b); h_new ----
    #pragma unroll
    for (int i = 0; i < 4; ++i)
        #pragma unroll
        for (int j = 0; j < 8; ++j) acc[i][j] = 0.0f;
    gemm_acc<8>(acc, W_ih + 1 * HID * HID, HID, HID, 8, As_x, HID, Wst, tid, c, rg4);
    gemm_acc<8>(acc, W_hh + 1 * HID * HID, HID, HID, 8, As_h, HID, Wst, tid, c, rg4);
    #pragma unroll
    for (int j = 0; j < 8; ++j) {
        int n = c + 32 * j;
        float b = b_ih[HID + n] + b_hh[HID + n];
        #pragma unroll
        for (int i = 0; i < 4; ++i) {
            int idx = (rg4 + i) * HID + n;
            float zg    = sigmoidf_(acc[i][j] + b);
            float hprev = As_h[idx];
            float hnew  = (1.0f - zg) * hn[i][j] + zg * hprev;
            out_h[(row0 + rg4 + i) * HID + n] = hnew;
            As_x[idx] = hnew;   // reuse As_x as h_new for the output head
        }
    }
    __syncthreads();

    // ---- P5: y = relu(h_new @ W_o1^T + b_o1) -> As_h ----
    #pragma unroll
    for (int i = 0; i < 4; ++i)
        #pragma unroll
        for (int j = 0; j < 8; ++j) acc[i][j] = 0.0f;
    gemm_acc<8>(acc, W_o1, HID, HID, 8, As_x, HID, Wst, tid, c, rg4);
    #pragma unroll
    for (int j = 0; j < 8; ++j) {
        int n = c + 32 * j;
        float b = b_o1[n];
        #pragma unroll
        for (int i = 0; i < 4; ++i)
            As_h[(rg4 + i) * HID + n] = fmaxf(acc[i][j] + b, 0.0f);
    }
    __syncthreads();

    // ---- P6: z_next = y @ W_o2^T + b_o2 (N = 64) ----
    float acc2[4][2];
    #pragma unroll
    for (int i = 0; i < 4; ++i) { acc2[i][0] = 0.0f; acc2[i][1] = 0.0f; }
    gemm_acc<2>(acc2, W_o2, HID, HID, 8, As_h, HID, Wst, tid, c, rg4);
    #pragma unroll
    for (int j = 0; j < 2; ++j) {
        int n = c + 32 * j;
        float b = b_o2[n];
        #pragma unroll
        for (int i = 0; i < 4; ++i)
            out_z[(row0 + rg4 + i) * LATENT + n] = acc2[i][j] + b;
    }
}

extern "C" void kernel_launch(void* const* d_in, const int* in_sizes, int n_in,
                              void* d_out, int out_size) {
    const float* z      = (const float*)d_in[0];
    const float* action = (const float*)d_in[1];
    const float* hidden = (const float*)d_in[2];
    const float* W_in   = (const float*)d_in[3];
    const float* b_in   = (const float*)d_in[4];
    const float* W_ih   = (const float*)d_in[5];
    const float* W_hh   = (const float*)d_in[6];
    const float* b_ih   = (const float*)d_in[7];
    const float* b_hh   = (const float*)d_in[8];
    const float* W_o1   = (const float*)d_in[9];
    const float* b_o1   = (const float*)d_in[10];
    const float* W_o2   = (const float*)d_in[11];
    const float* b_o2   = (const float*)d_in[12];

    const int B = in_sizes[0] / LATENT;   // 131072
    float* out_z = (float*)d_out;                      // [B, 64]
    float* out_h = (float*)d_out + (long)B * LATENT;   // [B, 256]

    // As_x (8192) + As_h (8192) + Wst (8224) floats = 96.1 KB -> 2 CTAs/SM
    const int smem_bytes = (2 * TM * HID + 32 * WST_LD) * sizeof(float);
    cudaFuncSetAttribute(latent_dynamics_kernel,
                         cudaFuncAttributeMaxDynamicSharedMemorySize, smem_bytes);

    dim3 grid(B / TM);
    latent_dynamics_kernel<<<grid, THREADS, smem_bytes>>>(
        z, action, hidden, W_in, b_in, W_ih, W_hh, b_ih, b_hh,
        W_o1, b_o1, W_o2, b_o2, out_z, out_h);
}

// round 9
// speedup vs baseline: 2.3494x; 1.9365x over previous
#include <cuda_runtime.h>
#include <cuda_bf16.h>
#include <cstdint>

// ============================================================================
// Fused LatentDynamicsModel on mma.sync (HMMA bf16, family-common PTX —
// tcgen05 is sm_103a arch-specific and this harness lowers via compute_103).
//
// Split-bf16 GEMMs: A = Ah + Al, B = Bh + Bl (bf16 each);
//   A@B ~= Ah@Bh + Al@Bh + Ah@Bl   (fp32 accumulate, err ~1e-5)
//
// Per CTA: 64 batch rows. Phases (R6 dataflow, all in one kernel):
//   P0 x=relu([z|a]W_in^T+b) -> X tiles     P1 hn = h Whh_n^T + b
//   P2 r=sigm(xWih_r+hWhh_r+b); hn*=r       P3 n=tanh(xWih_n+b+hn); hn=n
//   P4 zg=sigm(xWih_z+hWhh_z+b); h_new -> out_h + X tiles
//   P5 y=relu(h_new W_o1^T+b) -> H tiles    P6 z'=y W_o2^T + b -> out_z
// ============================================================================

#define TM      64
#define THREADS 256
#define BATCH   131072
#define LDA     264      // bf16 elems, A-tile stride (16B aligned, conflict-free)
#define LDW     40       // bf16 elems, W-tile stride
#define LDTO    264      // f32 stage stride

// smem byte offsets
#define OFF_XH  0
#define OFF_XL  33792
#define OFF_HH  67584
#define OFF_HL  101376
#define OFF_W0H 135168
#define OFF_W0L 155648
#define OFF_W1H 176128
#define OFF_W1L 196608
#define SMEM_TOTAL 217088
#define OFF_TO  OFF_W0H   // epilogue f32 staging (after gemm completes)

__device__ __forceinline__ uint32_t smem_to_u32(const void* p) {
    uint32_t a;
    asm("{ .reg .u64 t; cvta.to.shared.u64 t, %1; cvt.u32.u64 %0, t; }"
        : "=r"(a) : "l"(p));
    return a;
}

__device__ __forceinline__ void ldsm4(uint32_t* r, uint32_t addr) {
    asm volatile("ldmatrix.sync.aligned.m8n8.x4.shared.b16 {%0,%1,%2,%3}, [%4];"
                 : "=r"(r[0]), "=r"(r[1]), "=r"(r[2]), "=r"(r[3]) : "r"(addr));
}

__device__ __forceinline__ void mma16816(float* d, const uint32_t* a, const uint32_t* b) {
    asm volatile("mma.sync.aligned.m16n8k16.row.col.f32.bf16.bf16.f32 "
                 "{%0,%1,%2,%3}, {%4,%5,%6,%7}, {%8,%9}, {%0,%1,%2,%3};"
                 : "+f"(d[0]), "+f"(d[1]), "+f"(d[2]), "+f"(d[3])
                 : "r"(a[0]), "r"(a[1]), "r"(a[2]), "r"(a[3]),
                   "r"(b[0]), "r"(b[1]));
}

__device__ __forceinline__ void split2(float x, float y, uint32_t& hp, uint32_t& lp) {
    __nv_bfloat16 hx = __float2bfloat16(x), hy = __float2bfloat16(y);
    float rx = x - __bfloat162float(hx), ry = y - __bfloat162float(hy);
    __nv_bfloat16 lx = __float2bfloat16(rx), ly = __float2bfloat16(ry);
    hp = ((uint32_t)__bfloat16_as_ushort(hy) << 16) | __bfloat16_as_ushort(hx);
    lp = ((uint32_t)__bfloat16_as_ushort(ly) << 16) | __bfloat16_as_ushort(lx);
}
__device__ __forceinline__ float sigm(float x) { return 1.0f / (1.0f + __expf(-x)); }

// ---------------------------------------------------------------------------
// acc[4 mi][4 ni][4] += splitA(smem tiles) @ splitW(Wg)^T
// Wg row-major [NR x ldw], K = nchunks*32 cols. Warp w covers n in
// [warp_n0, warp_n0+32). Register-double-buffered W chunks through two smem
// ping-pong tiles. All threads participate in loads/barriers; warps with
// warp_n0 >= NR skip mma (P6).
// WIN: W_in bounds handling (66 real cols, zero-padded reads).
// ---------------------------------------------------------------------------
template <int NR, bool WIN>
__device__ void gemm_mma(float acc[4][4][4], char* sm, uint32_t sb,
                         uint32_t offAH, uint32_t offAL,
                         const float* __restrict__ Wg, int ldw, int nchunks,
                         int tid, int lane, int warp_n0)
{
    constexpr int NITER = NR / 32;        // float4 loads per thread per chunk
    uint32_t whi[2 * NITER], wlo[2 * NITER];

    auto loadW = [&](int c) {
        #pragma unroll
        for (int it = 0; it < NITER; ++it) {
            int i = tid + 256 * it;
            int row = i >> 3, q = i & 7;
            float v0, v1, v2, v3;
            if (WIN) {
                int col = c * 32 + q * 4;
                const float* p = Wg + (long)row * ldw;
                v0 = (col + 0 < 66) ? p[col + 0] : 0.0f;
                v1 = (col + 1 < 66) ? p[col + 1] : 0.0f;
                v2 = (col + 2 < 66) ? p[col + 2] : 0.0f;
                v3 = (col + 3 < 66) ? p[col + 3] : 0.0f;
            } else {
                float4 v = *reinterpret_cast<const float4*>(
                    Wg + (long)row * ldw + c * 32 + q * 4);
                v0 = v.x; v1 = v.y; v2 = v.z; v3 = v.w;
            }
            split2(v0, v1, whi[2 * it],     wlo[2 * it]);
            split2(v2, v3, whi[2 * it + 1], wlo[2 * it + 1]);
        }
    };
    auto storeW = [&](int buf) {
        uint32_t bh = buf ? OFF_W1H : OFF_W0H;
        uint32_t bl = buf ? OFF_W1L : OFF_W0L;
        #pragma unroll
        for (int it = 0; it < NITER; ++it) {
            int i = tid + 256 * it;
            int row = i >> 3, q = i & 7;
            *reinterpret_cast<uint2*>(sm + bh + row * 80 + q * 8) =
                make_uint2(whi[2 * it], whi[2 * it + 1]);
            *reinterpret_cast<uint2*>(sm + bl + row * 80 + q * 8) =
                make_uint2(wlo[2 * it], wlo[2 * it + 1]);
        }
    };

    loadW(0); storeW(0); __syncthreads();

    for (int c = 0; c < nchunks; ++c) {
        if (c + 1 < nchunks) loadW(c + 1);
        const uint32_t wbh = (c & 1) ? OFF_W1H : OFF_W0H;
        const uint32_t wbl = (c & 1) ? OFF_W1L : OFF_W0L;
        if (warp_n0 < NR) {
            const int mat = lane >> 3, r = lane & 7;
            #pragma unroll
            for (int ks = 0; ks < 2; ++ks) {
                const int kb = c * 32 + ks * 16;
                uint32_t ah[4][4], al[4][4];
                #pragma unroll
                for (int mi = 0; mi < 4; ++mi) {
                    int row = mi * 16 + (mat & 1) * 8 + r;
                    int col = kb + (mat >> 1) * 8;
                    uint32_t off = (uint32_t)(row * LDA + col) * 2;
                    ldsm4(ah[mi], sb + offAH + off);
                    ldsm4(al[mi], sb + offAL + off);
                }
                #pragma unroll
                for (int np = 0; np < 2; ++np) {
                    int n  = warp_n0 + (2 * np + (mat >> 1)) * 8 + r;
                    int kc = ks * 16 + (mat & 1) * 8;
                    uint32_t boff = (uint32_t)(n * LDW + kc) * 2;
                    uint32_t bh[4], bl[4];
                    ldsm4(bh, sb + wbh + boff);
                    ldsm4(bl, sb + wbl + boff);
                    #pragma unroll
                    for (int mi = 0; mi < 4; ++mi) {
                        mma16816(acc[mi][2 * np],     ah[mi], bh + 0);
                        mma16816(acc[mi][2 * np],     al[mi], bh + 0);
                        mma16816(acc[mi][2 * np],     ah[mi], bl + 0);
                        mma16816(acc[mi][2 * np + 1], ah[mi], bh + 2);
                        mma16816(acc[mi][2 * np + 1], al[mi], bh + 2);
                        mma16816(acc[mi][2 * np + 1], ah[mi], bl + 2);
                    }
                }
            }
        }
        if (c + 1 < nchunks) storeW((c + 1) & 1);
        __syncthreads();
    }
}

__device__ __forceinline__ void zero_acc(float a[4][4][4]) {
    #pragma unroll
    for (int i = 0; i < 4; ++i)
        #pragma unroll
        for (int j = 0; j < 4; ++j)
            #pragma unroll
            for (int k = 0; k < 4; ++k) a[i][j][k] = 0.0f;
}

__global__ __launch_bounds__(THREADS, 1)
void ldm_kernel(const float* __restrict__ z, const float* __restrict__ action,
                const float* __restrict__ hidden,
                const float* __restrict__ W_in, const float* __restrict__ b_in,
                const float* __restrict__ W_ih, const float* __restrict__ W_hh,
                const float* __restrict__ b_ih, const float* __restrict__ b_hh,
                const float* __restrict__ W_o1, const float* __restrict__ b_o1,
                const float* __restrict__ W_o2, const float* __restrict__ b_o2,
                float* __restrict__ out_z, float* __restrict__ out_h)
{
    extern __shared__ char sm[];
    const uint32_t sb = smem_to_u32(sm);
    const int tid = threadIdx.x, lane = tid & 31, warp = tid >> 5;
    const int warp_n0 = warp * 32;
    const int gid = lane >> 2, tig = lane & 3;
    const long row0 = (long)blockIdx.x * TM;

    __nv_bfloat16* XH = (__nv_bfloat16*)(sm + OFF_XH);
    __nv_bfloat16* XL = (__nv_bfloat16*)(sm + OFF_XL);
    __nv_bfloat16* HH = (__nv_bfloat16*)(sm + OFF_HH);
    __nv_bfloat16* HL = (__nv_bfloat16*)(sm + OFF_HL);

    // ---- init: za = [z|action|0] -> X tiles (cols 0..127), hidden -> H ----
    for (int i = tid; i < TM * 128; i += THREADS) {
        int r = i >> 7, c = i & 127;
        float v = 0.0f;
        if (c < 64)      v = z[(row0 + r) * 64 + c];
        else if (c < 66) v = action[(row0 + r) * 2 + (c - 64)];
        __nv_bfloat16 h = __float2bfloat16(v);
        XH[r * LDA + c] = h;
        XL[r * LDA + c] = __float2bfloat16(v - __bfloat162float(h));
    }
    for (int i = tid; i < TM * 256; i += THREADS) {
        int r = i >> 8, c = i & 255;
        float v = hidden[(row0 + r) * 256 + c];
        __nv_bfloat16 h = __float2bfloat16(v);
        HH[r * LDA + c] = h;
        HL[r * LDA + c] = __float2bfloat16(v - __bfloat162float(h));
    }
    __syncthreads();

    float acc[4][4][4], hn[4][4][4];

    // ================= P0: x = relu([z|a] @ W_in^T + b_in) =================
    zero_acc(acc);
    gemm_mma<256, true>(acc, sm, sb, OFF_XH, OFF_XL, W_in, 66, 3, tid, lane, warp_n0);
    #pragma unroll
    for (int mi = 0; mi < 4; ++mi)
        #pragma unroll
        for (int ni = 0; ni < 4; ++ni) {
            int col0 = warp_n0 + ni * 8 + tig * 2;
            int ra = mi * 16 + gid, rb = ra + 8;
            float v0 = fmaxf(acc[mi][ni][0] + b_in[col0],     0.0f);
            float v1 = fmaxf(acc[mi][ni][1] + b_in[col0 + 1], 0.0f);
            float v2 = fmaxf(acc[mi][ni][2] + b_in[col0],     0.0f);
            float v3 = fmaxf(acc[mi][ni][3] + b_in[col0 + 1], 0.0f);
            uint32_t hp, lp;
            split2(v0, v1, hp, lp);
            *(uint32_t*)(sm + OFF_XH + (ra * LDA + col0) * 2) = hp;
            *(uint32_t*)(sm + OFF_XL + (ra * LDA + col0) * 2) = lp;
            split2(v2, v3, hp, lp);
            *(uint32_t*)(sm + OFF_XH + (rb * LDA + col0) * 2) = hp;
            *(uint32_t*)(sm + OFF_XL + (rb * LDA + col0) * 2) = lp;
        }
    __syncthreads();

    // ================= P1: hn = h @ Whh_n^T + b_hh_n ========================
    zero_acc(acc);
    gemm_mma<256, false>(acc, sm, sb, OFF_HH, OFF_HL, W_hh + 512 * 256, 256, 8,
                         tid, lane, warp_n0);
    #pragma unroll
    for (int mi = 0; mi < 4; ++mi)
        #pragma unroll
        for (int ni = 0; ni < 4; ++ni) {
            int col0 = warp_n0 + ni * 8 + tig * 2;
            hn[mi][ni][0] = acc[mi][ni][0] + b_hh[512 + col0];
            hn[mi][ni][1] = acc[mi][ni][1] + b_hh[512 + col0 + 1];
            hn[mi][ni][2] = acc[mi][ni][2] + b_hh[512 + col0];
            hn[mi][ni][3] = acc[mi][ni][3] + b_hh[512 + col0 + 1];
        }

    // ================= P2: r gate; hn *= r ==================================
    zero_acc(acc);
    gemm_mma<256, false>(acc, sm, sb, OFF_XH, OFF_XL, W_ih, 256, 8, tid, lane, warp_n0);
    gemm_mma<256, false>(acc, sm, sb, OFF_HH, OFF_HL, W_hh, 256, 8, tid, lane, warp_n0);
    #pragma unroll
    for (int mi = 0; mi < 4; ++mi)
        #pragma unroll
        for (int ni = 0; ni < 4; ++ni) {
            int col0 = warp_n0 + ni * 8 + tig * 2;
            float b0 = b_ih[col0] + b_hh[col0];
            float b1 = b_ih[col0 + 1] + b_hh[col0 + 1];
            hn[mi][ni][0] *= sigm(acc[mi][ni][0] + b0);
            hn[mi][ni][1] *= sigm(acc[mi][ni][1] + b1);
            hn[mi][ni][2] *= sigm(acc[mi][ni][2] + b0);
            hn[mi][ni][3] *= sigm(acc[mi][ni][3] + b1);
        }

    // ================= P3: n = tanh(x@Wih_n + b + r*hn); hn = n =============
    zero_acc(acc);
    gemm_mma<256, false>(acc, sm, sb, OFF_XH, OFF_XL, W_ih + 512 * 256, 256, 8,
                         tid, lane, warp_n0);
    #pragma unroll
    for (int mi = 0; mi < 4; ++mi)
        #pragma unroll
        for (int ni = 0; ni < 4; ++ni) {
            int col0 = warp_n0 + ni * 8 + tig * 2;
            hn[mi][ni][0] = tanhf(acc[mi][ni][0] + b_ih[512 + col0]     + hn[mi][ni][0]);
            hn[mi][ni][1] = tanhf(acc[mi][ni][1] + b_ih[512 + col0 + 1] + hn[mi][ni][1]);
            hn[mi][ni][2] = tanhf(acc[mi][ni][2] + b_ih[512 + col0]     + hn[mi][ni][2]);
            hn[mi][ni][3] = tanhf(acc[mi][ni][3] + b_ih[512 + col0 + 1] + hn[mi][ni][3]);
        }

    // ================= P4: z gate; h_new ====================================
    zero_acc(acc);
    gemm_mma<256, false>(acc, sm, sb, OFF_XH, OFF_XL, W_ih + 256 * 256, 256, 8,
                         tid, lane, warp_n0);
    gemm_mma<256, false>(acc, sm, sb, OFF_HH, OFF_HL, W_hh + 256 * 256, 256, 8,
                         tid, lane, warp_n0);
    {
        float* TO = (float*)(sm + OFF_TO);
        #pragma unroll
        for (int mi = 0; mi < 4; ++mi)
            #pragma unroll
            for (int ni = 0; ni < 4; ++ni) {
                int col0 = warp_n0 + ni * 8 + tig * 2;
                int ra = mi * 16 + gid, rb = ra + 8;
                float bz0 = b_ih[256 + col0] + b_hh[256 + col0];
                float bz1 = b_ih[256 + col0 + 1] + b_hh[256 + col0 + 1];
                #pragma unroll
                for (int cc = 0; cc < 4; ++cc) {
                    int row = (cc < 2) ? ra : rb;
                    int col = col0 + (cc & 1);
                    float zg = sigm(acc[mi][ni][cc] + ((cc & 1) ? bz1 : bz0));
                    float h  = __bfloat162float(HH[row * LDA + col]) +
                               __bfloat162float(HL[row * LDA + col]);
                    TO[row * LDTO + col] = (1.0f - zg) * hn[mi][ni][cc] + zg * h;
                }
            }
        __syncthreads();
        // coalesced out_h store + refill X tiles with split(h_new)
        for (int i = tid; i < TM * 256; i += THREADS) {
            int r = i >> 8, c = i & 255;
            float v = TO[r * LDTO + c];
            out_h[(row0 + r) * 256 + c] = v;
            __nv_bfloat16 h = __float2bfloat16(v);
            XH[r * LDA + c] = h;
            XL[r * LDA + c] = __float2bfloat16(v - __bfloat162float(h));
        }
        __syncthreads();
    }

    // ================= P5: y = relu(h_new @ W_o1^T + b_o1) -> H tiles =======
    zero_acc(acc);
    gemm_mma<256, false>(acc, sm, sb, OFF_XH, OFF_XL, W_o1, 256, 8, tid, lane, warp_n0);
    #pragma unroll
    for (int mi = 0; mi < 4; ++mi)
        #pragma unroll
        for (int ni = 0; ni < 4; ++ni) {
            int col0 = warp_n0 + ni * 8 + tig * 2;
            int ra = mi * 16 + gid, rb = ra + 8;
            float v0 = fmaxf(acc[mi][ni][0] + b_o1[col0],     0.0f);
            float v1 = fmaxf(acc[mi][ni][1] + b_o1[col0 + 1], 0.0f);
            float v2 = fmaxf(acc[mi][ni][2] + b_o1[col0],     0.0f);
            float v3 = fmaxf(acc[mi][ni][3] + b_o1[col0 + 1], 0.0f);
            uint32_t hp, lp;
            split2(v0, v1, hp, lp);
            *(uint32_t*)(sm + OFF_HH + (ra * LDA + col0) * 2) = hp;
            *(uint32_t*)(sm + OFF_HL + (ra * LDA + col0) * 2) = lp;
            split2(v2, v3, hp, lp);
            *(uint32_t*)(sm + OFF_HH + (rb * LDA + col0) * 2) = hp;
            *(uint32_t*)(sm + OFF_HL + (rb * LDA + col0) * 2) = lp;
        }
    __syncthreads();

    // ================= P6: z_next = y @ W_o2^T + b_o2 (N=64) ================
    zero_acc(acc);
    gemm_mma<64, false>(acc, sm, sb, OFF_HH, OFF_HL, W_o2, 256, 8, tid, lane, warp_n0);
    {
        float* TO = (float*)(sm + OFF_TO);
        if (warp_n0 < 64) {
            #pragma unroll
            for (int mi = 0; mi < 4; ++mi)
                #pragma unroll
                for (int ni = 0; ni < 4; ++ni) {
                    int col0 = warp_n0 + ni * 8 + tig * 2;
                    int ra = mi * 16 + gid, rb = ra + 8;
                    TO[ra * 68 + col0]     = acc[mi][ni][0] + b_o2[col0];
                    TO[ra * 68 + col0 + 1] = acc[mi][ni][1] + b_o2[col0 + 1];
                    TO[rb * 68 + col0]     = acc[mi][ni][2] + b_o2[col0];
                    TO[rb * 68 + col0 + 1] = acc[mi][ni][3] + b_o2[col0 + 1];
                }
        }
        __syncthreads();
        for (int i = tid; i < TM * 64; i += THREADS) {
            int r = i >> 6, c = i & 63;
            out_z[(row0 + r) * 64 + c] = TO[r * 68 + c];
        }
    }
}

// ============================== launch ======================================

extern "C" void kernel_launch(void* const* d_in, const int* in_sizes, int n_in,
                              void* d_out, int out_size) {
    const float* z      = (const float*)d_in[0];
    const float* action = (const float*)d_in[1];
    const float* hidden = (const float*)d_in[2];
    const float* W_in   = (const float*)d_in[3];
    const float* b_in   = (const float*)d_in[4];
    const float* W_ih   = (const float*)d_in[5];
    const float* W_hh   = (const float*)d_in[6];
    const float* b_ih   = (const float*)d_in[7];
    const float* b_hh   = (const float*)d_in[8];
    const float* W_o1   = (const float*)d_in[9];
    const float* b_o1   = (const float*)d_in[10];
    const float* W_o2   = (const float*)d_in[11];
    const float* b_o2   = (const float*)d_in[12];

    float* out_z = (float*)d_out;                       // [B, 64]
    float* out_h = (float*)d_out + (long)BATCH * 64;    // [B, 256]

    cudaFuncSetAttribute(ldm_kernel,
                         cudaFuncAttributeMaxDynamicSharedMemorySize, SMEM_TOTAL);

    dim3 grid(BATCH / TM);
    ldm_kernel<<<grid, THREADS, SMEM_TOTAL>>>(
        z, action, hidden, W_in, b_in, W_ih, W_hh, b_ih, b_hh,
        W_o1, b_o1, W_o2, b_o2, out_z, out_h);
}

// round 10
// speedup vs baseline: 3.2534x; 1.3848x over previous
#include <cuda_runtime.h>
#include <cuda_bf16.h>
#include <cstdint>

// ============================================================================
// Fused LatentDynamicsModel, split-bf16 mma.sync (family-common PTX).
// R10: 512 threads (16 warps, 2x8 warp grid), weights pre-split to bf16 hi/lo
// in __device__ scratch, cp.async double-buffered weight chunks.
//
//   A@B ~= Ah@Bh + Al@Bh + Ah@Bl   (fp32 accumulate, err ~1e-5)
//
// Per CTA: 64 batch rows. Phases:
//   P0 x=relu([z|a]W_in^T+b)      P1 hn = h Whh_n^T + b
//   P2 r gate; hn*=r              P3 n=tanh(xWih_n+b+hn); hn=n
//   P4 z gate; h_new -> out_h     P5 y=relu(h_new W_o1^T+b)
//   P6 z'=y W_o2^T + b -> out_z
// ============================================================================

#define TM      64
#define THREADS 512
#define BATCH   131072
#define LDA     264      // bf16 elems, A-tile stride
#define LDTO    264      // f32 stage stride

// ---- pre-split weight scratch (bf16 hi/lo), element offsets ----
#define OFF_WIN 0
#define OFF_WIH (OFF_WIN + 256 * 128)
#define OFF_WHH (OFF_WIH + 768 * 256)
#define OFF_WO1 (OFF_WHH + 768 * 256)
#define OFF_WO2 (OFF_WO1 + 256 * 256)
#define W_TOTAL (OFF_WO2 + 64 * 256)

__device__ __align__(16) __nv_bfloat16 g_Whi[W_TOTAL];
__device__ __align__(16) __nv_bfloat16 g_Wlo[W_TOTAL];

// ---- smem byte offsets ----
#define OFF_XH  0
#define OFF_XL  33792
#define OFF_HH  67584
#define OFF_HL  101376
#define OFF_W0H 135168            // 256 rows x 80B
#define OFF_W0L 155648
#define OFF_W1H 176128
#define OFF_W1L 196608
#define SMEM_TOTAL 217088
#define OFF_TO  OFF_W0H           // epilogue f32 staging (gemm idle)

__device__ __forceinline__ uint32_t smem_to_u32(const void* p) {
    uint32_t a;
    asm("{ .reg .u64 t; cvta.to.shared.u64 t, %1; cvt.u32.u64 %0, t; }"
        : "=r"(a) : "l"(p));
    return a;
}
__device__ __forceinline__ void ldsm4(uint32_t* r, uint32_t addr) {
    asm volatile("ldmatrix.sync.aligned.m8n8.x4.shared.b16 {%0,%1,%2,%3}, [%4];"
                 : "=r"(r[0]), "=r"(r[1]), "=r"(r[2]), "=r"(r[3]) : "r"(addr));
}
__device__ __forceinline__ void mma16816(float* d, const uint32_t* a, const uint32_t* b) {
    asm volatile("mma.sync.aligned.m16n8k16.row.col.f32.bf16.bf16.f32 "
                 "{%0,%1,%2,%3}, {%4,%5,%6,%7}, {%8,%9}, {%0,%1,%2,%3};"
                 : "+f"(d[0]), "+f"(d[1]), "+f"(d[2]), "+f"(d[3])
                 : "r"(a[0]), "r"(a[1]), "r"(a[2]), "r"(a[3]),
                   "r"(b[0]), "r"(b[1]));
}
__device__ __forceinline__ void split2(float x, float y, uint32_t& hp, uint32_t& lp) {
    __nv_bfloat16 hx = __float2bfloat16(x), hy = __float2bfloat16(y);
    float rx = x - __bfloat162float(hx), ry = y - __bfloat162float(hy);
    __nv_bfloat16 lx = __float2bfloat16(rx), ly = __float2bfloat16(ry);
    hp = ((uint32_t)__bfloat16_as_ushort(hy) << 16) | __bfloat16_as_ushort(hx);
    lp = ((uint32_t)__bfloat16_as_ushort(ly) << 16) | __bfloat16_as_ushort(lx);
}
__device__ __forceinline__ float sigm(float x) { return 1.0f / (1.0f + __expf(-x)); }

// ======================= weight conversion kernel ===========================
__global__ void wconv_kernel(const float* __restrict__ W_in,
                             const float* __restrict__ W_ih,
                             const float* __restrict__ W_hh,
                             const float* __restrict__ W_o1,
                             const float* __restrict__ W_o2) {
    for (long i = (long)blockIdx.x * blockDim.x + threadIdx.x; i < W_TOTAL;
         i += (long)gridDim.x * blockDim.x) {
        float v;
        if (i < OFF_WIH)      { long r = i >> 7, c = i & 127;
                                v = (c < 66) ? W_in[r * 66 + c] : 0.0f; }
        else if (i < OFF_WHH)   v = W_ih[i - OFF_WIH];
        else if (i < OFF_WO1)   v = W_hh[i - OFF_WHH];
        else if (i < OFF_WO2)   v = W_o1[i - OFF_WO1];
        else                    v = W_o2[i - OFF_WO2];
        __nv_bfloat16 h = __float2bfloat16(v);
        g_Whi[i] = h;
        g_Wlo[i] = __float2bfloat16(v - __bfloat162float(h));
    }
}

// ---------------------------------------------------------------------------
// acc[2 mi][4 ni][4] += splitA(smem) @ splitW(global bf16 hi/lo)^T
// Weight chunks [NR x 32] cp.async double-buffered into SMEM ping-pong.
// Warp (warp_m, warp_n0): rows warp_m*32 + mi*16..., cols warp_n0..+32.
// ---------------------------------------------------------------------------
template <int NR>
__device__ void gemm_mma(float acc[2][4][4], uint32_t sb,
                         uint32_t offAH, uint32_t offAL,
                         const __nv_bfloat16* __restrict__ Wh,
                         const __nv_bfloat16* __restrict__ Wl,
                         int ldw, int nchunks,
                         int tid, int lane, int warp_m, int warp_n0)
{
    constexpr int NXFER = NR * 8;              // 16B transfers (hi+lo) per chunk
    constexpr int NITER = NXFER / THREADS;     // per-thread

    auto issue = [&](int c, int b) {
        const uint32_t bh = b ? OFF_W1H : OFF_W0H;
        const uint32_t bl = b ? OFF_W1L : OFF_W0L;
        #pragma unroll
        for (int it = 0; it < NITER; ++it) {
            int i = tid + THREADS * it;        // [0, NR*8)
            int half = (i >= NR * 4) ? 1 : 0;  // 0=hi 1=lo
            int j = i - half * NR * 4;
            int row = j >> 2, q = j & 3;
            const __nv_bfloat16* src =
                (half ? Wl : Wh) + (long)row * ldw + c * 32 + q * 8;
            uint32_t dst = sb + (half ? bl : bh) + row * 80 + q * 16;
            asm volatile("cp.async.ca.shared.global [%0], [%1], 16;"
                         :: "r"(dst), "l"(src));
        }
        asm volatile("cp.async.commit_group;" ::: "memory");
    };

    issue(0, 0);
    for (int c = 0; c < nchunks; ++c) {
        asm volatile("cp.async.wait_group 0;" ::: "memory");
        __syncthreads();                    // chunk c visible; prev compute done
        if (c + 1 < nchunks) issue(c + 1, (c + 1) & 1);

        const uint32_t wbh = (c & 1) ? OFF_W1H : OFF_W0H;
        const uint32_t wbl = (c & 1) ? OFF_W1L : OFF_W0L;
        if (warp_n0 < NR) {
            const int mat = lane >> 3, r = lane & 7;
            #pragma unroll
            for (int ks = 0; ks < 2; ++ks) {
                uint32_t ah[2][4], al[2][4];
                #pragma unroll
                for (int mi = 0; mi < 2; ++mi) {
                    int row = warp_m * 32 + mi * 16 + (mat & 1) * 8 + r;
                    int col = c * 32 + ks * 16 + (mat >> 1) * 8;
                    uint32_t off = (uint32_t)(row * LDA + col) * 2;
                    ldsm4(ah[mi], sb + offAH + off);
                    ldsm4(al[mi], sb + offAL + off);
                }
                #pragma unroll
                for (int np = 0; np < 2; ++np) {
                    int n  = warp_n0 + (2 * np + (mat >> 1)) * 8 + r;
                    int kc = ks * 16 + (mat & 1) * 8;
                    uint32_t boff = (uint32_t)(n * 80 + kc * 2);
                    uint32_t bh[4], bl[4];
                    ldsm4(bh, sb + wbh + boff);
                    ldsm4(bl, sb + wbl + boff);
                    #pragma unroll
                    for (int mi = 0; mi < 2; ++mi) {
                        mma16816(acc[mi][2 * np],     ah[mi], bh + 0);
                        mma16816(acc[mi][2 * np],     al[mi], bh + 0);
                        mma16816(acc[mi][2 * np],     ah[mi], bl + 0);
                        mma16816(acc[mi][2 * np + 1], ah[mi], bh + 2);
                        mma16816(acc[mi][2 * np + 1], al[mi], bh + 2);
                        mma16816(acc[mi][2 * np + 1], ah[mi], bl + 2);
                    }
                }
            }
        }
    }
    __syncthreads();   // all mma reads of smem done before caller reuses tiles
}

__device__ __forceinline__ void zero_acc(float a[2][4][4]) {
    #pragma unroll
    for (int i = 0; i < 2; ++i)
        #pragma unroll
        for (int j = 0; j < 4; ++j)
            #pragma unroll
            for (int k = 0; k < 4; ++k) a[i][j][k] = 0.0f;
}

__global__ __launch_bounds__(THREADS, 1)
void ldm_kernel(const float* __restrict__ z, const float* __restrict__ action,
                const float* __restrict__ hidden,
                const float* __restrict__ b_in,
                const float* __restrict__ b_ih, const float* __restrict__ b_hh,
                const float* __restrict__ b_o1, const float* __restrict__ b_o2,
                float* __restrict__ out_z, float* __restrict__ out_h)
{
    extern __shared__ char sm[];
    const uint32_t sb = smem_to_u32(sm);
    const int tid = threadIdx.x, lane = tid & 31, warp = tid >> 5;
    const int warp_m = warp & 1, warp_n0 = (warp >> 1) * 32;
    const int gid = lane >> 2, tig = lane & 3;
    const long row0 = (long)blockIdx.x * TM;

    __nv_bfloat16* XH = (__nv_bfloat16*)(sm + OFF_XH);
    __nv_bfloat16* XL = (__nv_bfloat16*)(sm + OFF_XL);
    __nv_bfloat16* HH = (__nv_bfloat16*)(sm + OFF_HH);
    __nv_bfloat16* HL = (__nv_bfloat16*)(sm + OFF_HL);

    // ---- init: za = [z|action|0] -> X cols 0..127, hidden -> H ----
    for (int i = tid; i < TM * 128; i += THREADS) {
        int r = i >> 7, c = i & 127;
        float v = 0.0f;
        if (c < 64)      v = z[(row0 + r) * 64 + c];
        else if (c < 66) v = action[(row0 + r) * 2 + (c - 64)];
        __nv_bfloat16 h = __float2bfloat16(v);
        XH[r * LDA + c] = h;
        XL[r * LDA + c] = __float2bfloat16(v - __bfloat162float(h));
    }
    for (int i = tid; i < TM * 256; i += THREADS) {
        int r = i >> 8, c = i & 255;
        float v = hidden[(row0 + r) * 256 + c];
        __nv_bfloat16 h = __float2bfloat16(v);
        HH[r * LDA + c] = h;
        HL[r * LDA + c] = __float2bfloat16(v - __bfloat162float(h));
    }
    __syncthreads();

    float acc[2][4][4], hn[2][4][4];

    // ================= P0: x = relu([z|a] @ W_in^T + b_in) =================
    zero_acc(acc);
    gemm_mma<256>(acc, sb, OFF_XH, OFF_XL,
                  g_Whi + OFF_WIN, g_Wlo + OFF_WIN, 128, 4,
                  tid, lane, warp_m, warp_n0);
    #pragma unroll
    for (int mi = 0; mi < 2; ++mi)
        #pragma unroll
        for (int ni = 0; ni < 4; ++ni) {
            int col0 = warp_n0 + ni * 8 + tig * 2;
            int ra = warp_m * 32 + mi * 16 + gid, rb = ra + 8;
            float v0 = fmaxf(acc[mi][ni][0] + b_in[col0],     0.0f);
            float v1 = fmaxf(acc[mi][ni][1] + b_in[col0 + 1], 0.0f);
            float v2 = fmaxf(acc[mi][ni][2] + b_in[col0],     0.0f);
            float v3 = fmaxf(acc[mi][ni][3] + b_in[col0 + 1], 0.0f);
            uint32_t hp, lp;
            split2(v0, v1, hp, lp);
            *(uint32_t*)(sm + OFF_XH + (ra * LDA + col0) * 2) = hp;
            *(uint32_t*)(sm + OFF_XL + (ra * LDA + col0) * 2) = lp;
            split2(v2, v3, hp, lp);
            *(uint32_t*)(sm + OFF_XH + (rb * LDA + col0) * 2) = hp;
            *(uint32_t*)(sm + OFF_XL + (rb * LDA + col0) * 2) = lp;
        }
    __syncthreads();

    // ================= P1: hn = h @ Whh_n^T + b_hh_n ========================
    zero_acc(acc);
    gemm_mma<256>(acc, sb, OFF_HH, OFF_HL,
                  g_Whi + OFF_WHH + 512 * 256, g_Wlo + OFF_WHH + 512 * 256, 256, 8,
                  tid, lane, warp_m, warp_n0);
    #pragma unroll
    for (int mi = 0; mi < 2; ++mi)
        #pragma unroll
        for (int ni = 0; ni < 4; ++ni) {
            int col0 = warp_n0 + ni * 8 + tig * 2;
            hn[mi][ni][0] = acc[mi][ni][0] + b_hh[512 + col0];
            hn[mi][ni][1] = acc[mi][ni][1] + b_hh[512 + col0 + 1];
            hn[mi][ni][2] = acc[mi][ni][2] + b_hh[512 + col0];
            hn[mi][ni][3] = acc[mi][ni][3] + b_hh[512 + col0 + 1];
        }

    // ================= P2: r gate; hn *= r ==================================
    zero_acc(acc);
    gemm_mma<256>(acc, sb, OFF_XH, OFF_XL,
                  g_Whi + OFF_WIH, g_Wlo + OFF_WIH, 256, 8,
                  tid, lane, warp_m, warp_n0);
    gemm_mma<256>(acc, sb, OFF_HH, OFF_HL,
                  g_Whi + OFF_WHH, g_Wlo + OFF_WHH, 256, 8,
                  tid, lane, warp_m, warp_n0);
    #pragma unroll
    for (int mi = 0; mi < 2; ++mi)
        #pragma unroll
        for (int ni = 0; ni < 4; ++ni) {
            int col0 = warp_n0 + ni * 8 + tig * 2;
            float b0 = b_ih[col0] + b_hh[col0];
            float b1 = b_ih[col0 + 1] + b_hh[col0 + 1];
            hn[mi][ni][0] *= sigm(acc[mi][ni][0] + b0);
            hn[mi][ni][1] *= sigm(acc[mi][ni][1] + b1);
            hn[mi][ni][2] *= sigm(acc[mi][ni][2] + b0);
            hn[mi][ni][3] *= sigm(acc[mi][ni][3] + b1);
        }

    // ================= P3: n = tanh(x@Wih_n + b + r*hn); hn = n =============
    zero_acc(acc);
    gemm_mma<256>(acc, sb, OFF_XH, OFF_XL,
                  g_Whi + OFF_WIH + 512 * 256, g_Wlo + OFF_WIH + 512 * 256, 256, 8,
                  tid, lane, warp_m, warp_n0);
    #pragma unroll
    for (int mi = 0; mi < 2; ++mi)
        #pragma unroll
        for (int ni = 0; ni < 4; ++ni) {
            int col0 = warp_n0 + ni * 8 + tig * 2;
            hn[mi][ni][0] = tanhf(acc[mi][ni][0] + b_ih[512 + col0]     + hn[mi][ni][0]);
            hn[mi][ni][1] = tanhf(acc[mi][ni][1] + b_ih[512 + col0 + 1] + hn[mi][ni][1]);
            hn[mi][ni][2] = tanhf(acc[mi][ni][2] + b_ih[512 + col0]     + hn[mi][ni][2]);
            hn[mi][ni][3] = tanhf(acc[mi][ni][3] + b_ih[512 + col0 + 1] + hn[mi][ni][3]);
        }

    // ================= P4: z gate; h_new ====================================
    zero_acc(acc);
    gemm_mma<256>(acc, sb, OFF_XH, OFF_XL,
                  g_Whi + OFF_WIH + 256 * 256, g_Wlo + OFF_WIH + 256 * 256, 256, 8,
                  tid, lane, warp_m, warp_n0);
    gemm_mma<256>(acc, sb, OFF_HH, OFF_HL,
                  g_Whi + OFF_WHH + 256 * 256, g_Wlo + OFF_WHH + 256 * 256, 256, 8,
                  tid, lane, warp_m, warp_n0);
    {
        float* TO = (float*)(sm + OFF_TO);
        #pragma unroll
        for (int mi = 0; mi < 2; ++mi)
            #pragma unroll
            for (int ni = 0; ni < 4; ++ni) {
                int col0 = warp_n0 + ni * 8 + tig * 2;
                int ra = warp_m * 32 + mi * 16 + gid, rb = ra + 8;
                float bz0 = b_ih[256 + col0] + b_hh[256 + col0];
                float bz1 = b_ih[256 + col0 + 1] + b_hh[256 + col0 + 1];
                #pragma unroll
                for (int cc = 0; cc < 4; ++cc) {
                    int row = (cc < 2) ? ra : rb;
                    int col = col0 + (cc & 1);
                    float zg = sigm(acc[mi][ni][cc] + ((cc & 1) ? bz1 : bz0));
                    float h  = __bfloat162float(HH[row * LDA + col]) +
                               __bfloat162float(HL[row * LDA + col]);
                    TO[row * LDTO + col] = (1.0f - zg) * hn[mi][ni][cc] + zg * h;
                }
            }
        __syncthreads();
        for (int i = tid; i < TM * 256; i += THREADS) {
            int r = i >> 8, c = i & 255;
            float v = TO[r * LDTO + c];
            out_h[(row0 + r) * 256 + c] = v;
            __nv_bfloat16 h = __float2bfloat16(v);
            XH[r * LDA + c] = h;
            XL[r * LDA + c] = __float2bfloat16(v - __bfloat162float(h));
        }
        __syncthreads();
    }

    // ================= P5: y = relu(h_new @ W_o1^T + b_o1) -> H tiles =======
    zero_acc(acc);
    gemm_mma<256>(acc, sb, OFF_XH, OFF_XL,
                  g_Whi + OFF_WO1, g_Wlo + OFF_WO1, 256, 8,
                  tid, lane, warp_m, warp_n0);
    #pragma unroll
    for (int mi = 0; mi < 2; ++mi)
        #pragma unroll
        for (int ni = 0; ni < 4; ++ni) {
            int col0 = warp_n0 + ni * 8 + tig * 2;
            int ra = warp_m * 32 + mi * 16 + gid, rb = ra + 8;
            float v0 = fmaxf(acc[mi][ni][0] + b_o1[col0],     0.0f);
            float v1 = fmaxf(acc[mi][ni][1] + b_o1[col0 + 1], 0.0f);
            float v2 = fmaxf(acc[mi][ni][2] + b_o1[col0],     0.0f);
            float v3 = fmaxf(acc[mi][ni][3] + b_o1[col0 + 1], 0.0f);
            uint32_t hp, lp;
            split2(v0, v1, hp, lp);
            *(uint32_t*)(sm + OFF_HH + (ra * LDA + col0) * 2) = hp;
            *(uint32_t*)(sm + OFF_HL + (ra * LDA + col0) * 2) = lp;
            split2(v2, v3, hp, lp);
            *(uint32_t*)(sm + OFF_HH + (rb * LDA + col0) * 2) = hp;
            *(uint32_t*)(sm + OFF_HL + (rb * LDA + col0) * 2) = lp;
        }
    __syncthreads();

    // ================= P6: z_next = y @ W_o2^T + b_o2 (N=64) ================
    zero_acc(acc);
    gemm_mma<64>(acc, sb, OFF_HH, OFF_HL,
                 g_Whi + OFF_WO2, g_Wlo + OFF_WO2, 256, 8,
                 tid, lane, warp_m, warp_n0);
    {
        float* TO = (float*)(sm + OFF_TO);
        if (warp_n0 < 64) {
            #pragma unroll
            for (int mi = 0; mi < 2; ++mi)
                #pragma unroll
                for (int ni = 0; ni < 4; ++ni) {
                    int col0 = warp_n0 + ni * 8 + tig * 2;
                    int ra = warp_m * 32 + mi * 16 + gid, rb = ra + 8;
                    TO[ra * 68 + col0]     = acc[mi][ni][0] + b_o2[col0];
                    TO[ra * 68 + col0 + 1] = acc[mi][ni][1] + b_o2[col0 + 1];
                    TO[rb * 68 + col0]     = acc[mi][ni][2] + b_o2[col0];
                    TO[rb * 68 + col0 + 1] = acc[mi][ni][3] + b_o2[col0 + 1];
                }
        }
        __syncthreads();
        for (int i = tid; i < TM * 64; i += THREADS) {
            int r = i >> 6, c = i & 63;
            out_z[(row0 + r) * 64 + c] = TO[r * 68 + c];
        }
    }
}

// ============================== launch ======================================

extern "C" void kernel_launch(void* const* d_in, const int* in_sizes, int n_in,
                              void* d_out, int out_size) {
    const float* z      = (const float*)d_in[0];
    const float* action = (const float*)d_in[1];
    const float* hidden = (const float*)d_in[2];
    const float* W_in   = (const float*)d_in[3];
    const float* b_in   = (const float*)d_in[4];
    const float* W_ih   = (const float*)d_in[5];
    const float* W_hh   = (const float*)d_in[6];
    const float* b_ih   = (const float*)d_in[7];
    const float* b_hh   = (const float*)d_in[8];
    const float* W_o1   = (const float*)d_in[9];
    const float* b_o1   = (const float*)d_in[10];
    const float* W_o2   = (const float*)d_in[11];
    const float* b_o2   = (const float*)d_in[12];

    float* out_z = (float*)d_out;                       // [B, 64]
    float* out_h = (float*)d_out + (long)BATCH * 64;    // [B, 256]

    cudaFuncSetAttribute(ldm_kernel,
                         cudaFuncAttributeMaxDynamicSharedMemorySize, SMEM_TOTAL);

    wconv_kernel<<<256, 256>>>(W_in, W_ih, W_hh, W_o1, W_o2);
    dim3 grid(BATCH / TM);
    ldm_kernel<<<grid, THREADS, SMEM_TOTAL>>>(
        z, action, hidden, b_in, b_ih, b_hh, b_o1, b_o2, out_z, out_h);
}

// round 11
// speedup vs baseline: 3.2545x; 1.0003x over previous
#include <cuda_runtime.h>
#include <cuda_bf16.h>
#include <cstdint>

// ============================================================================
// Fused LatentDynamicsModel, split-bf16 mma.sync (family-common PTX).
// R11: inner-loop restructure — per-k16 fragment preload + term-outermost mma
// ordering (same-acc reuse distance 1 -> 8) to break HMMA RAW serialization.
//
//   A@B ~= Ah@Bh + Al@Bh + Ah@Bl   (fp32 accumulate, err ~1e-5)
// ============================================================================

#define TM      64
#define THREADS 512
#define BATCH   131072
#define LDA     264      // bf16 elems, A-tile stride
#define LDTO    264      // f32 stage stride

// ---- pre-split weight scratch (bf16 hi/lo), element offsets ----
#define OFF_WIN 0
#define OFF_WIH (OFF_WIN + 256 * 128)
#define OFF_WHH (OFF_WIH + 768 * 256)
#define OFF_WO1 (OFF_WHH + 768 * 256)
#define OFF_WO2 (OFF_WO1 + 256 * 256)
#define W_TOTAL (OFF_WO2 + 64 * 256)

__device__ __align__(16) __nv_bfloat16 g_Whi[W_TOTAL];
__device__ __align__(16) __nv_bfloat16 g_Wlo[W_TOTAL];

// ---- smem byte offsets ----
#define OFF_XH  0
#define OFF_XL  33792
#define OFF_HH  67584
#define OFF_HL  101376
#define OFF_W0H 135168            // 256 rows x 80B
#define OFF_W0L 155648
#define OFF_W1H 176128
#define OFF_W1L 196608
#define SMEM_TOTAL 217088
#define OFF_TO  OFF_W0H           // epilogue f32 staging (gemm idle)

__device__ __forceinline__ uint32_t smem_to_u32(const void* p) {
    uint32_t a;
    asm("{ .reg .u64 t; cvta.to.shared.u64 t, %1; cvt.u32.u64 %0, t; }"
        : "=r"(a) : "l"(p));
    return a;
}
__device__ __forceinline__ void ldsm4(uint32_t* r, uint32_t addr) {
    asm volatile("ldmatrix.sync.aligned.m8n8.x4.shared.b16 {%0,%1,%2,%3}, [%4];"
                 : "=r"(r[0]), "=r"(r[1]), "=r"(r[2]), "=r"(r[3]) : "r"(addr));
}
__device__ __forceinline__ void mma16816(float* d, const uint32_t* a, const uint32_t* b) {
    asm volatile("mma.sync.aligned.m16n8k16.row.col.f32.bf16.bf16.f32 "
                 "{%0,%1,%2,%3}, {%4,%5,%6,%7}, {%8,%9}, {%0,%1,%2,%3};"
                 : "+f"(d[0]), "+f"(d[1]), "+f"(d[2]), "+f"(d[3])
                 : "r"(a[0]), "r"(a[1]), "r"(a[2]), "r"(a[3]),
                   "r"(b[0]), "r"(b[1]));
}
__device__ __forceinline__ void split2(float x, float y, uint32_t& hp, uint32_t& lp) {
    __nv_bfloat16 hx = __float2bfloat16(x), hy = __float2bfloat16(y);
    float rx = x - __bfloat162float(hx), ry = y - __bfloat162float(hy);
    __nv_bfloat16 lx = __float2bfloat16(rx), ly = __float2bfloat16(ry);
    hp = ((uint32_t)__bfloat16_as_ushort(hy) << 16) | __bfloat16_as_ushort(hx);
    lp = ((uint32_t)__bfloat16_as_ushort(ly) << 16) | __bfloat16_as_ushort(lx);
}
__device__ __forceinline__ float sigm(float x) { return 1.0f / (1.0f + __expf(-x)); }

// ======================= weight conversion kernel ===========================
__global__ void wconv_kernel(const float* __restrict__ W_in,
                             const float* __restrict__ W_ih,
                             const float* __restrict__ W_hh,
                             const float* __restrict__ W_o1,
                             const float* __restrict__ W_o2) {
    for (long i = (long)blockIdx.x * blockDim.x + threadIdx.x; i < W_TOTAL;
         i += (long)gridDim.x * blockDim.x) {
        float v;
        if (i < OFF_WIH)      { long r = i >> 7, c = i & 127;
                                v = (c < 66) ? W_in[r * 66 + c] : 0.0f; }
        else if (i < OFF_WHH)   v = W_ih[i - OFF_WIH];
        else if (i < OFF_WO1)   v = W_hh[i - OFF_WHH];
        else if (i < OFF_WO2)   v = W_o1[i - OFF_WO1];
        else                    v = W_o2[i - OFF_WO2];
        __nv_bfloat16 h = __float2bfloat16(v);
        g_Whi[i] = h;
        g_Wlo[i] = __float2bfloat16(v - __bfloat162float(h));
    }
}

// ---------------------------------------------------------------------------
// acc[2 mi][4 ni][4] += splitA(smem) @ splitW(global bf16 hi/lo)^T
// Weight chunks [NR x 32] cp.async double-buffered into SMEM ping-pong.
// Inner: per-k16 fragment preload, then 24 mmas ordered term-outermost so the
// same accumulator is revisited only every 8 mmas.
// ---------------------------------------------------------------------------
template <int NR>
__device__ void gemm_mma(float acc[2][4][4], uint32_t sb,
                         uint32_t offAH, uint32_t offAL,
                         const __nv_bfloat16* __restrict__ Wh,
                         const __nv_bfloat16* __restrict__ Wl,
                         int ldw, int nchunks,
                         int tid, int lane, int warp_m, int warp_n0)
{
    constexpr int NXFER = NR * 8;              // 16B transfers (hi+lo) per chunk
    constexpr int NITER = NXFER / THREADS;     // per-thread

    auto issue = [&](int c, int b) {
        const uint32_t bhof = b ? OFF_W1H : OFF_W0H;
        const uint32_t blof = b ? OFF_W1L : OFF_W0L;
        #pragma unroll
        for (int it = 0; it < NITER; ++it) {
            int i = tid + THREADS * it;        // [0, NR*8)
            int half = (i >= NR * 4) ? 1 : 0;  // 0=hi 1=lo
            int j = i - half * NR * 4;
            int row = j >> 2, q = j & 3;
            const __nv_bfloat16* src =
                (half ? Wl : Wh) + (long)row * ldw + c * 32 + q * 8;
            uint32_t dst = sb + (half ? blof : bhof) + row * 80 + q * 16;
            asm volatile("cp.async.ca.shared.global [%0], [%1], 16;"
                         :: "r"(dst), "l"(src));
        }
        asm volatile("cp.async.commit_group;" ::: "memory");
    };

    issue(0, 0);
    for (int c = 0; c < nchunks; ++c) {
        asm volatile("cp.async.wait_group 0;" ::: "memory");
        __syncthreads();                    // chunk c visible; prev compute done
        if (c + 1 < nchunks) issue(c + 1, (c + 1) & 1);

        const uint32_t wbh = (c & 1) ? OFF_W1H : OFF_W0H;
        const uint32_t wbl = (c & 1) ? OFF_W1L : OFF_W0L;
        if (warp_n0 < NR) {
            const int mat = lane >> 3, r = lane & 7;
            #pragma unroll
            for (int ks = 0; ks < 2; ++ks) {
                // ---- preload ALL fragments for this k16 step ----
                uint32_t ah[2][4], al[2][4];      // A hi/lo, 2 m-subtiles
                uint32_t bh[2][4], bl[2][4];      // B hi/lo, 2 np groups
                #pragma unroll
                for (int mi = 0; mi < 2; ++mi) {
                    int row = warp_m * 32 + mi * 16 + (mat & 1) * 8 + r;
                    int col = c * 32 + ks * 16 + (mat >> 1) * 8;
                    uint32_t off = (uint32_t)(row * LDA + col) * 2;
                    ldsm4(ah[mi], sb + offAH + off);
                    ldsm4(al[mi], sb + offAL + off);
                }
                #pragma unroll
                for (int np = 0; np < 2; ++np) {
                    int n  = warp_n0 + (2 * np + (mat >> 1)) * 8 + r;
                    int kc = ks * 16 + (mat & 1) * 8;
                    uint32_t boff = (uint32_t)(n * 80 + kc * 2);
                    ldsm4(bh[np], sb + wbh + boff);
                    ldsm4(bl[np], sb + wbl + boff);
                }
                // ---- 24 mmas, term-outermost: acc reuse distance = 8 ----
                #pragma unroll
                for (int t = 0; t < 3; ++t) {
                    #pragma unroll
                    for (int np = 0; np < 2; ++np) {
                        #pragma unroll
                        for (int hf = 0; hf < 2; ++hf) {
                            const uint32_t* bp =
                                (t == 2 ? bl[np] : bh[np]) + 2 * hf;
                            #pragma unroll
                            for (int mi = 0; mi < 2; ++mi) {
                                const uint32_t* ap = (t == 1) ? al[mi] : ah[mi];
                                mma16816(acc[mi][2 * np + hf], ap, bp);
                            }
                        }
                    }
                }
            }
        }
    }
    __syncthreads();   // all mma reads of smem done before caller reuses tiles
}

__device__ __forceinline__ void zero_acc(float a[2][4][4]) {
    #pragma unroll
    for (int i = 0; i < 2; ++i)
        #pragma unroll
        for (int j = 0; j < 4; ++j)
            #pragma unroll
            for (int k = 0; k < 4; ++k) a[i][j][k] = 0.0f;
}

__global__ __launch_bounds__(THREADS, 1)
void ldm_kernel(const float* __restrict__ z, const float* __restrict__ action,
                const float* __restrict__ hidden,
                const float* __restrict__ b_in,
                const float* __restrict__ b_ih, const float* __restrict__ b_hh,
                const float* __restrict__ b_o1, const float* __restrict__ b_o2,
                float* __restrict__ out_z, float* __restrict__ out_h)
{
    extern __shared__ char sm[];
    const uint32_t sb = smem_to_u32(sm);
    const int tid = threadIdx.x, lane = tid & 31, warp = tid >> 5;
    const int warp_m = warp & 1, warp_n0 = (warp >> 1) * 32;
    const int gid = lane >> 2, tig = lane & 3;
    const long row0 = (long)blockIdx.x * TM;

    __nv_bfloat16* XH = (__nv_bfloat16*)(sm + OFF_XH);
    __nv_bfloat16* XL = (__nv_bfloat16*)(sm + OFF_XL);
    __nv_bfloat16* HH = (__nv_bfloat16*)(sm + OFF_HH);
    __nv_bfloat16* HL = (__nv_bfloat16*)(sm + OFF_HL);

    // ---- init: za = [z|action|0] -> X cols 0..127, hidden -> H ----
    for (int i = tid; i < TM * 128; i += THREADS) {
        int r = i >> 7, c = i & 127;
        float v = 0.0f;
        if (c < 64)      v = z[(row0 + r) * 64 + c];
        else if (c < 66) v = action[(row0 + r) * 2 + (c - 64)];
        __nv_bfloat16 h = __float2bfloat16(v);
        XH[r * LDA + c] = h;
        XL[r * LDA + c] = __float2bfloat16(v - __bfloat162float(h));
    }
    for (int i = tid; i < TM * 256; i += THREADS) {
        int r = i >> 8, c = i & 255;
        float v = hidden[(row0 + r) * 256 + c];
        __nv_bfloat16 h = __float2bfloat16(v);
        HH[r * LDA + c] = h;
        HL[r * LDA + c] = __float2bfloat16(v - __bfloat162float(h));
    }
    __syncthreads();

    float acc[2][4][4], hn[2][4][4];

    // ================= P0: x = relu([z|a] @ W_in^T + b_in) =================
    zero_acc(acc);
    gemm_mma<256>(acc, sb, OFF_XH, OFF_XL,
                  g_Whi + OFF_WIN, g_Wlo + OFF_WIN, 128, 4,
                  tid, lane, warp_m, warp_n0);
    #pragma unroll
    for (int mi = 0; mi < 2; ++mi)
        #pragma unroll
        for (int ni = 0; ni < 4; ++ni) {
            int col0 = warp_n0 + ni * 8 + tig * 2;
            int ra = warp_m * 32 + mi * 16 + gid, rb = ra + 8;
            float v0 = fmaxf(acc[mi][ni][0] + b_in[col0],     0.0f);
            float v1 = fmaxf(acc[mi][ni][1] + b_in[col0 + 1], 0.0f);
            float v2 = fmaxf(acc[mi][ni][2] + b_in[col0],     0.0f);
            float v3 = fmaxf(acc[mi][ni][3] + b_in[col0 + 1], 0.0f);
            uint32_t hp, lp;
            split2(v0, v1, hp, lp);
            *(uint32_t*)(sm + OFF_XH + (ra * LDA + col0) * 2) = hp;
            *(uint32_t*)(sm + OFF_XL + (ra * LDA + col0) * 2) = lp;
            split2(v2, v3, hp, lp);
            *(uint32_t*)(sm + OFF_XH + (rb * LDA + col0) * 2) = hp;
            *(uint32_t*)(sm + OFF_XL + (rb * LDA + col0) * 2) = lp;
        }
    __syncthreads();

    // ================= P1: hn = h @ Whh_n^T + b_hh_n ========================
    zero_acc(acc);
    gemm_mma<256>(acc, sb, OFF_HH, OFF_HL,
                  g_Whi + OFF_WHH + 512 * 256, g_Wlo + OFF_WHH + 512 * 256, 256, 8,
                  tid, lane, warp_m, warp_n0);
    #pragma unroll
    for (int mi = 0; mi < 2; ++mi)
        #pragma unroll
        for (int ni = 0; ni < 4; ++ni) {
            int col0 = warp_n0 + ni * 8 + tig * 2;
            hn[mi][ni][0] = acc[mi][ni][0] + b_hh[512 + col0];
            hn[mi][ni][1] = acc[mi][ni][1] + b_hh[512 + col0 + 1];
            hn[mi][ni][2] = acc[mi][ni][2] + b_hh[512 + col0];
            hn[mi][ni][3] = acc[mi][ni][3] + b_hh[512 + col0 + 1];
        }

    // ================= P2: r gate; hn *= r ==================================
    zero_acc(acc);
    gemm_mma<256>(acc, sb, OFF_XH, OFF_XL,
                  g_Whi + OFF_WIH, g_Wlo + OFF_WIH, 256, 8,
                  tid, lane, warp_m, warp_n0);
    gemm_mma<256>(acc, sb, OFF_HH, OFF_HL,
                  g_Whi + OFF_WHH, g_Wlo + OFF_WHH, 256, 8,
                  tid, lane, warp_m, warp_n0);
    #pragma unroll
    for (int mi = 0; mi < 2; ++mi)
        #pragma unroll
        for (int ni = 0; ni < 4; ++ni) {
            int col0 = warp_n0 + ni * 8 + tig * 2;
            float b0 = b_ih[col0] + b_hh[col0];
            float b1 = b_ih[col0 + 1] + b_hh[col0 + 1];
            hn[mi][ni][0] *= sigm(acc[mi][ni][0] + b0);
            hn[mi][ni][1] *= sigm(acc[mi][ni][1] + b1);
            hn[mi][ni][2] *= sigm(acc[mi][ni][2] + b0);
            hn[mi][ni][3] *= sigm(acc[mi][ni][3] + b1);
        }

    // ================= P3: n = tanh(x@Wih_n + b + r*hn); hn = n =============
    zero_acc(acc);
    gemm_mma<256>(acc, sb, OFF_XH, OFF_XL,
                  g_Whi + OFF_WIH + 512 * 256, g_Wlo + OFF_WIH + 512 * 256, 256, 8,
                  tid, lane, warp_m, warp_n0);
    #pragma unroll
    for (int mi = 0; mi < 2; ++mi)
        #pragma unroll
        for (int ni = 0; ni < 4; ++ni) {
            int col0 = warp_n0 + ni * 8 + tig * 2;
            hn[mi][ni][0] = tanhf(acc[mi][ni][0] + b_ih[512 + col0]     + hn[mi][ni][0]);
            hn[mi][ni][1] = tanhf(acc[mi][ni][1] + b_ih[512 + col0 + 1] + hn[mi][ni][1]);
            hn[mi][ni][2] = tanhf(acc[mi][ni][2] + b_ih[512 + col0]     + hn[mi][ni][2]);
            hn[mi][ni][3] = tanhf(acc[mi][ni][3] + b_ih[512 + col0 + 1] + hn[mi][ni][3]);
        }

    // ================= P4: z gate; h_new ====================================
    zero_acc(acc);
    gemm_mma<256>(acc, sb, OFF_XH, OFF_XL,
                  g_Whi + OFF_WIH + 256 * 256, g_Wlo + OFF_WIH + 256 * 256, 256, 8,
                  tid, lane, warp_m, warp_n0);
    gemm_mma<256>(acc, sb, OFF_HH, OFF_HL,
                  g_Whi + OFF_WHH + 256 * 256, g_Wlo + OFF_WHH + 256 * 256, 256, 8,
                  tid, lane, warp_m, warp_n0);
    {
        float* TO = (float*)(sm + OFF_TO);
        #pragma unroll
        for (int mi = 0; mi < 2; ++mi)
            #pragma unroll
            for (int ni = 0; ni < 4; ++ni) {
                int col0 = warp_n0 + ni * 8 + tig * 2;
                int ra = warp_m * 32 + mi * 16 + gid, rb = ra + 8;
                float bz0 = b_ih[256 + col0] + b_hh[256 + col0];
                float bz1 = b_ih[256 + col0 + 1] + b_hh[256 + col0 + 1];
                #pragma unroll
                for (int cc = 0; cc < 4; ++cc) {
                    int row = (cc < 2) ? ra : rb;
                    int col = col0 + (cc & 1);
                    float zg = sigm(acc[mi][ni][cc] + ((cc & 1) ? bz1 : bz0));
                    float h  = __bfloat162float(HH[row * LDA + col]) +
                               __bfloat162float(HL[row * LDA + col]);
                    TO[row * LDTO + col] = (1.0f - zg) * hn[mi][ni][cc] + zg * h;
                }
            }
        __syncthreads();
        for (int i = tid; i < TM * 256; i += THREADS) {
            int r = i >> 8, c = i & 255;
            float v = TO[r * LDTO + c];
            out_h[(row0 + r) * 256 + c] = v;
            __nv_bfloat16 h = __float2bfloat16(v);
            XH[r * LDA + c] = h;
            XL[r * LDA + c] = __float2bfloat16(v - __bfloat162float(h));
        }
        __syncthreads();
    }

    // ================= P5: y = relu(h_new @ W_o1^T + b_o1) -> H tiles =======
    zero_acc(acc);
    gemm_mma<256>(acc, sb, OFF_XH, OFF_XL,
                  g_Whi + OFF_WO1, g_Wlo + OFF_WO1, 256, 8,
                  tid, lane, warp_m, warp_n0);
    #pragma unroll
    for (int mi = 0; mi < 2; ++mi)
        #pragma unroll
        for (int ni = 0; ni < 4; ++ni) {
            int col0 = warp_n0 + ni * 8 + tig * 2;
            int ra = warp_m * 32 + mi * 16 + gid, rb = ra + 8;
            float v0 = fmaxf(acc[mi][ni][0] + b_o1[col0],     0.0f);
            float v1 = fmaxf(acc[mi][ni][1] + b_o1[col0 + 1], 0.0f);
            float v2 = fmaxf(acc[mi][ni][2] + b_o1[col0],     0.0f);
            float v3 = fmaxf(acc[mi][ni][3] + b_o1[col0 + 1], 0.0f);
            uint32_t hp, lp;
            split2(v0, v1, hp, lp);
            *(uint32_t*)(sm + OFF_HH + (ra * LDA + col0) * 2) = hp;
            *(uint32_t*)(sm + OFF_HL + (ra * LDA + col0) * 2) = lp;
            split2(v2, v3, hp, lp);
            *(uint32_t*)(sm + OFF_HH + (rb * LDA + col0) * 2) = hp;
            *(uint32_t*)(sm + OFF_HL + (rb * LDA + col0) * 2) = lp;
        }
    __syncthreads();

    // ================= P6: z_next = y @ W_o2^T + b_o2 (N=64) ================
    zero_acc(acc);
    gemm_mma<64>(acc, sb, OFF_HH, OFF_HL,
                 g_Whi + OFF_WO2, g_Wlo + OFF_WO2, 256, 8,
                 tid, lane, warp_m, warp_n0);
    {
        float* TO = (float*)(sm + OFF_TO);
        if (warp_n0 < 64) {
            #pragma unroll
            for (int mi = 0; mi < 2; ++mi)
                #pragma unroll
                for (int ni = 0; ni < 4; ++ni) {
                    int col0 = warp_n0 + ni * 8 + tig * 2;
                    int ra = warp_m * 32 + mi * 16 + gid, rb = ra + 8;
                    TO[ra * 68 + col0]     = acc[mi][ni][0] + b_o2[col0];
                    TO[ra * 68 + col0 + 1] = acc[mi][ni][1] + b_o2[col0 + 1];
                    TO[rb * 68 + col0]     = acc[mi][ni][2] + b_o2[col0];
                    TO[rb * 68 + col0 + 1] = acc[mi][ni][3] + b_o2[col0 + 1];
                }
        }
        __syncthreads();
        for (int i = tid; i < TM * 64; i += THREADS) {
            int r = i >> 6, c = i & 63;
            out_z[(row0 + r) * 64 + c] = TO[r * 68 + c];
        }
    }
}

// ============================== launch ======================================

extern "C" void kernel_launch(void* const* d_in, const int* in_sizes, int n_in,
                              void* d_out, int out_size) {
    const float* z      = (const float*)d_in[0];
    const float* action = (const float*)d_in[1];
    const float* hidden = (const float*)d_in[2];
    const float* W_in   = (const float*)d_in[3];
    const float* b_in   = (const float*)d_in[4];
    const float* W_ih   = (const float*)d_in[5];
    const float* W_hh   = (const float*)d_in[6];
    const float* b_ih   = (const float*)d_in[7];
    const float* b_hh   = (const float*)d_in[8];
    const float* W_o1   = (const float*)d_in[9];
    const float* b_o1   = (const float*)d_in[10];
    const float* W_o2   = (const float*)d_in[11];
    const float* b_o2   = (const float*)d_in[12];

    float* out_z = (float*)d_out;                       // [B, 64]
    float* out_h = (float*)d_out + (long)BATCH * 64;    // [B, 256]

    cudaFuncSetAttribute(ldm_kernel,
                         cudaFuncAttributeMaxDynamicSharedMemorySize, SMEM_TOTAL);

    wconv_kernel<<<256, 256>>>(W_in, W_ih, W_hh, W_o1, W_o2);
    dim3 grid(BATCH / TM);
    ldm_kernel<<<grid, THREADS, SMEM_TOTAL>>>(
        z, action, hidden, b_in, b_ih, b_hh, b_o1, b_o2, out_z, out_h);
}